// round 3
// baseline (speedup 1.0000x reference)
#include <cuda_runtime.h>
#include <cstdint>

#define NMAX 100000
#define EMAX 1600000
#define F_IN 512
#define H1DIM 64   // 8 heads * 8
#define NHEAD 8
#define HDIM 8
#define NC 10
#define SLOPE 0.2f
#define EPSV 1e-16f

// ---------------- scratch (device globals, no allocation) ----------------
__device__ float g_h1[(size_t)NMAX * H1DIM];
__device__ float g_asrc1[(size_t)NMAX * NHEAD];
__device__ float g_adst1[(size_t)NMAX * NHEAD];
__device__ float g_max1[(size_t)NMAX * NHEAD];
__device__ float g_den1[(size_t)NMAX * NHEAD];
__device__ float g_acc1[(size_t)NMAX * H1DIM];
__device__ float g_h2[(size_t)NMAX * H1DIM];
__device__ float g_z2[(size_t)NMAX * NC];
__device__ float g_as2[NMAX];
__device__ float g_ad2[NMAX];
__device__ float g_max2[NMAX];
__device__ float g_den2[NMAX];
__device__ float g_acc2[(size_t)NMAX * NC];
__device__ int   g_idx64;   // 1 if edge_index is int64, 0 if int32

// ---------------- helpers ----------------
__device__ __forceinline__ float atomicMaxFloat(float* addr, float value) {
    if (value >= 0.0f)
        return __int_as_float(atomicMax((int*)addr, __float_as_int(value)));
    else
        return __uint_as_float(atomicMin((unsigned int*)addr, __float_as_uint(value)));
}

__device__ __forceinline__ float lrelu(float x) { return x > 0.0f ? x : SLOPE * x; }

__device__ __forceinline__ void load_edge(const void* ei, long E, long idx,
                                          int& s, int& d) {
    if (idx >= E) { s = d = (int)(idx - E); return; }  // self-loop
    if (g_idx64) {
        const long long* p = (const long long*)ei;
        s = (int)p[idx];
        d = (int)p[E + idx];
    } else {
        const int* p = (const int*)ei;
        s = p[idx];
        d = p[E + idx];
    }
}

// ---------------- kernels ----------------

// detect edge_index dtype: int64 -> high 32-bit words are all zero (indices < 1e5)
__global__ void detect_idx_kernel(const unsigned int* ei) {
    int is64 = 1;
    for (int i = 0; i < 64; i++) {
        if (ei[2 * i + 1] != 0u) { is64 = 0; break; }
    }
    g_idx64 = is64;
}

__global__ void init_kernel(int N) {
    long i = (long)blockIdx.x * blockDim.x + threadIdx.x;
    long stride = (long)gridDim.x * blockDim.x;
    const float NEGINF = __int_as_float(0xff800000);
    for (long t = i; t < (long)N * NHEAD; t += stride) { g_max1[t] = NEGINF; g_den1[t] = 0.0f; }
    for (long t = i; t < (long)N * H1DIM; t += stride) g_acc1[t] = 0.0f;
    for (long t = i; t < N; t += stride) { g_max2[t] = NEGINF; g_den2[t] = 0.0f; }
    for (long t = i; t < (long)N * NC; t += stride) g_acc2[t] = 0.0f;
}

// SGEMM: H[N,64] = X[N,512] @ W[512,64]   (BM=128, BN=64, BK=16, 256 thr, 8x4 microtile)
__global__ void gemm1_kernel(const float* __restrict__ X, const float* __restrict__ W,
                             int N) {
    __shared__ float As[16][128];
    __shared__ float Bs[16][64];
    int tid = threadIdx.x;
    int blockRow = blockIdx.x * 128;
    int ty = tid >> 4;          // 0..15
    int tx = tid & 15;          // 0..15
    int aRow = tid >> 2;        // 0..63
    int aCol = (tid & 3) * 4;   // 0,4,8,12
    int bRow = tid >> 4;        // 0..15
    int bCol = (tid & 15) * 4;  // 0..60

    float acc[8][4];
#pragma unroll
    for (int i = 0; i < 8; i++)
#pragma unroll
        for (int j = 0; j < 4; j++) acc[i][j] = 0.0f;

    for (int k0 = 0; k0 < F_IN; k0 += 16) {
#pragma unroll
        for (int r = 0; r < 2; r++) {
            int row = blockRow + aRow + r * 64;
            float4 v = make_float4(0.f, 0.f, 0.f, 0.f);
            if (row < N) v = *(const float4*)(X + (long)row * F_IN + k0 + aCol);
            As[aCol + 0][aRow + r * 64] = v.x;
            As[aCol + 1][aRow + r * 64] = v.y;
            As[aCol + 2][aRow + r * 64] = v.z;
            As[aCol + 3][aRow + r * 64] = v.w;
        }
        *(float4*)&Bs[bRow][bCol] = *(const float4*)(W + (long)(k0 + bRow) * 64 + bCol);
        __syncthreads();
#pragma unroll
        for (int k = 0; k < 16; k++) {
            float a[8], b[4];
            float4 a0 = *(const float4*)&As[k][ty * 8];
            float4 a1 = *(const float4*)&As[k][ty * 8 + 4];
            a[0] = a0.x; a[1] = a0.y; a[2] = a0.z; a[3] = a0.w;
            a[4] = a1.x; a[5] = a1.y; a[6] = a1.z; a[7] = a1.w;
            float4 b0 = *(const float4*)&Bs[k][tx * 4];
            b[0] = b0.x; b[1] = b0.y; b[2] = b0.z; b[3] = b0.w;
#pragma unroll
            for (int i = 0; i < 8; i++)
#pragma unroll
                for (int j = 0; j < 4; j++) acc[i][j] = fmaf(a[i], b[j], acc[i][j]);
        }
        __syncthreads();
    }
#pragma unroll
    for (int i = 0; i < 8; i++) {
        int row = blockRow + ty * 8 + i;
        if (row < N) {
            float4 v = make_float4(acc[i][0], acc[i][1], acc[i][2], acc[i][3]);
            *(float4*)(g_h1 + (long)row * 64 + tx * 4) = v;
        }
    }
}

// per (node, head): attention dot products
__global__ void attn1_kernel(const float* __restrict__ asrc, const float* __restrict__ adst,
                             int N) {
    int gid = blockIdx.x * blockDim.x + threadIdx.x;
    if (gid >= N * NHEAD) return;
    int n = gid >> 3, h = gid & 7;
    float s = 0.0f, d = 0.0f;
#pragma unroll
    for (int j = 0; j < HDIM; j++) {
        float hv = g_h1[(long)n * H1DIM + h * HDIM + j];
        s = fmaf(hv, asrc[h * HDIM + j], s);
        d = fmaf(hv, adst[h * HDIM + j], d);
    }
    g_asrc1[gid] = s;
    g_adst1[gid] = d;
}

__global__ void edge_max1_kernel(const void* __restrict__ ei, long E, int N) {
    long idx = (long)blockIdx.x * blockDim.x + threadIdx.x;
    long Etot = E + N;
    if (idx >= Etot) return;
    int s, d;
    load_edge(ei, E, idx, s, d);
#pragma unroll
    for (int h = 0; h < NHEAD; h++) {
        float e = lrelu(g_asrc1[(long)s * NHEAD + h] + g_adst1[(long)d * NHEAD + h]);
        atomicMaxFloat(&g_max1[(long)d * NHEAD + h], e);
    }
}

// warp per edge; lane handles channels lane and lane+32
__global__ void edge_agg1_kernel(const void* __restrict__ ei, long E, int N) {
    long widx = ((long)blockIdx.x * blockDim.x + threadIdx.x) >> 5;
    int lane = threadIdx.x & 31;
    long Etot = E + N;
    if (widx >= Etot) return;
    int s, d;
    load_edge(ei, E, widx, s, d);
#pragma unroll
    for (int half = 0; half < 2; half++) {
        int c = lane + 32 * half;
        int h = c >> 3;
        float e = lrelu(g_asrc1[(long)s * NHEAD + h] + g_adst1[(long)d * NHEAD + h]);
        float p = expf(e - g_max1[(long)d * NHEAD + h]);
        atomicAdd(&g_acc1[(long)d * H1DIM + c], p * g_h1[(long)s * H1DIM + c]);
        if ((c & 7) == 0) atomicAdd(&g_den1[(long)d * NHEAD + h], p);
    }
}

__global__ void finalize1_kernel(const float* __restrict__ b1, int N) {
    long t = (long)blockIdx.x * blockDim.x + threadIdx.x;
    if (t >= (long)N * H1DIM) return;
    int n = (int)(t >> 6), c = (int)(t & 63);
    int h = c >> 3;
    float v = g_acc1[t] / (g_den1[(long)n * NHEAD + h] + EPSV) + b1[c];
    g_h2[t] = v > 0.0f ? v : (expf(v) - 1.0f);  // ELU
}

// warp per node: z = h2 @ W2 (K=64, 10 classes) + attention scalars
__global__ void gemm2_kernel(const float* __restrict__ W2, const float* __restrict__ as2v,
                             const float* __restrict__ ad2v, int N) {
    long warp = ((long)blockIdx.x * blockDim.x + threadIdx.x) >> 5;
    int lane = threadIdx.x & 31;
    if (warp >= N) return;
    const float* hrow = g_h2 + warp * H1DIM;
    float z = 0.0f;
    if (lane < NC) {
#pragma unroll
        for (int k = 0; k < H1DIM; k++) z = fmaf(hrow[k], W2[k * NC + lane], z);
        g_z2[warp * NC + lane] = z;
    }
    float s = (lane < NC) ? z * as2v[lane] : 0.0f;
    float d = (lane < NC) ? z * ad2v[lane] : 0.0f;
#pragma unroll
    for (int off = 16; off > 0; off >>= 1) {
        s += __shfl_down_sync(0xffffffff, s, off);
        d += __shfl_down_sync(0xffffffff, d, off);
    }
    if (lane == 0) { g_as2[warp] = s; g_ad2[warp] = d; }
}

__global__ void edge_max2_kernel(const void* __restrict__ ei, long E, int N) {
    long idx = (long)blockIdx.x * blockDim.x + threadIdx.x;
    long Etot = E + N;
    if (idx >= Etot) return;
    int s, d;
    load_edge(ei, E, idx, s, d);
    float e = lrelu(g_as2[s] + g_ad2[d]);
    atomicMaxFloat(&g_max2[d], e);
}

__global__ void edge_agg2_kernel(const void* __restrict__ ei, long E, int N) {
    long idx = (long)blockIdx.x * blockDim.x + threadIdx.x;
    long Etot = E + N;
    if (idx >= Etot) return;
    int s, d;
    load_edge(ei, E, idx, s, d);
    float e = lrelu(g_as2[s] + g_ad2[d]);
    float p = expf(e - g_max2[d]);
    atomicAdd(&g_den2[d], p);
#pragma unroll
    for (int c = 0; c < NC; c++)
        atomicAdd(&g_acc2[(long)d * NC + c], p * g_z2[(long)s * NC + c]);
}

__global__ void finalize2_kernel(const float* __restrict__ b2, float* __restrict__ out,
                                 int N) {
    int n = blockIdx.x * blockDim.x + threadIdx.x;
    if (n >= N) return;
    float v[NC];
    float den = g_den2[n] + EPSV;
    float m = __int_as_float(0xff800000);
#pragma unroll
    for (int c = 0; c < NC; c++) {
        v[c] = g_acc2[(long)n * NC + c] / den + b2[c];
        m = fmaxf(m, v[c]);
    }
    float s = 0.0f;
#pragma unroll
    for (int c = 0; c < NC; c++) s += expf(v[c] - m);
    float lse = logf(s);
#pragma unroll
    for (int c = 0; c < NC; c++) out[(long)n * NC + c] = v[c] - m - lse;
}

// ---------------- launch ----------------
extern "C" void kernel_launch(void* const* d_in, const int* in_sizes, int n_in,
                              void* d_out, int out_size) {
    const float* x    = (const float*)d_in[0];
    const float* W1   = (const float*)d_in[1];
    const float* as1  = (const float*)d_in[2];
    const float* ad1  = (const float*)d_in[3];
    const float* b1   = (const float*)d_in[4];
    const float* W2   = (const float*)d_in[5];
    const float* as2  = (const float*)d_in[6];
    const float* ad2  = (const float*)d_in[7];
    const float* b2   = (const float*)d_in[8];
    const void*  ei   = d_in[9];
    float* out = (float*)d_out;

    int N = in_sizes[0] / F_IN;
    long E = (long)in_sizes[9] / 2;
    long Etot = E + N;

    detect_idx_kernel<<<1, 1>>>((const unsigned int*)ei);
    init_kernel<<<4096, 256>>>(N);

    gemm1_kernel<<<(N + 127) / 128, 256>>>(x, W1, N);
    attn1_kernel<<<(N * NHEAD + 255) / 256, 256>>>(as1, ad1, N);

    edge_max1_kernel<<<(unsigned)((Etot + 255) / 256), 256>>>(ei, E, N);
    edge_agg1_kernel<<<(unsigned)((Etot * 32 + 255) / 256), 256>>>(ei, E, N);
    finalize1_kernel<<<(unsigned)(((long)N * H1DIM + 255) / 256), 256>>>(b1, N);

    gemm2_kernel<<<(unsigned)(((long)N * 32 + 255) / 256), 256>>>(W2, as2, ad2, N);
    edge_max2_kernel<<<(unsigned)((Etot + 255) / 256), 256>>>(ei, E, N);
    edge_agg2_kernel<<<(unsigned)((Etot + 255) / 256), 256>>>(ei, E, N);
    finalize2_kernel<<<(N + 255) / 256, 256>>>(b2, out, N);
}

// round 5
// speedup vs baseline: 1.7476x; 1.7476x over previous
#include <cuda_runtime.h>
#include <cstdint>

#define NMAX 100000
#define EMAX 1600000
#define F_IN 512
#define H1DIM 64   // 8 heads * 8
#define NHEAD 8
#define HDIM 8
#define NC 10
#define SLOPE 0.2f
#define EPSV 1e-16f
#define ETOTMAX (EMAX + NMAX)

// ---------------- scratch (device globals, no allocation) ----------------
__device__ float g_h1[(size_t)NMAX * H1DIM];
__device__ float g_asrc1[(size_t)NMAX * NHEAD];
__device__ float g_adst1[(size_t)NMAX * NHEAD];
__device__ float g_h2[(size_t)NMAX * H1DIM];
__device__ float g_z2[(size_t)NMAX * NC];
__device__ float g_as2[NMAX];
__device__ float g_ad2[NMAX];
__device__ int   g_idx64;        // 1 if edge_index is int64, 0 if int32

// CSR build scratch
__device__ int g_deg[NMAX];
__device__ int g_rowptr[NMAX + 1];
__device__ int g_cursor[NMAX];
__device__ int g_bsum[1024];
__device__ int g_bsumx[1024];
__device__ int g_srcs[ETOTMAX];

// ---------------- helpers ----------------
__device__ __forceinline__ float lrelu(float x) { return x > 0.0f ? x : SLOPE * x; }

__device__ __forceinline__ void load_edge(const void* ei, long E, long idx,
                                          int& s, int& d) {
    if (idx >= E) { s = d = (int)(idx - E); return; }  // self-loop
    if (g_idx64) {
        const long long* p = (const long long*)ei;
        s = (int)p[idx];
        d = (int)p[E + idx];
    } else {
        const int* p = (const int*)ei;
        s = p[idx];
        d = p[E + idx];
    }
}

__device__ __forceinline__ int load_dst(const void* ei, long E, long idx) {
    if (idx >= E) return (int)(idx - E);
    if (g_idx64) return (int)((const long long*)ei)[E + idx];
    return ((const int*)ei)[E + idx];
}

// ---------------- kernels ----------------

// detect edge_index dtype: int64 -> high 32-bit words are all zero (indices < 1e5)
__global__ void detect_idx_kernel(const unsigned int* ei) {
    int is64 = 1;
    for (int i = 0; i < 64; i++) {
        if (ei[2 * i + 1] != 0u) { is64 = 0; break; }
    }
    g_idx64 = is64;
}

__global__ void zero_deg_kernel(int N) {
    int i = blockIdx.x * blockDim.x + threadIdx.x;
    if (i < N) g_deg[i] = 0;
}

__global__ void hist_kernel(const void* __restrict__ ei, long E, int N) {
    long idx = (long)blockIdx.x * blockDim.x + threadIdx.x;
    if (idx >= E + N) return;
    int d = load_dst(ei, E, idx);
    atomicAdd(&g_deg[d], 1);
}

// block-level exclusive scan of g_deg -> g_rowptr (local), block totals -> g_bsum
__global__ void scan1_kernel(int N) {
    __shared__ int sh[256];
    int tid = threadIdx.x;
    int i = blockIdx.x * 256 + tid;
    int v = (i < N) ? g_deg[i] : 0;
    sh[tid] = v;
    __syncthreads();
#pragma unroll
    for (int off = 1; off < 256; off <<= 1) {
        int t = (tid >= off) ? sh[tid - off] : 0;
        __syncthreads();
        sh[tid] += t;
        __syncthreads();
    }
    if (i < N) g_rowptr[i] = sh[tid] - v;     // exclusive
    if (tid == 255) g_bsum[blockIdx.x] = sh[tid];
}

// single-block scan of block sums (nblk <= 512)
__global__ void scan2_kernel(int nblk) {
    __shared__ int sh[512];
    int tid = threadIdx.x;
    int v = (tid < nblk) ? g_bsum[tid] : 0;
    sh[tid] = v;
    __syncthreads();
#pragma unroll
    for (int off = 1; off < 512; off <<= 1) {
        int t = (tid >= off) ? sh[tid - off] : 0;
        __syncthreads();
        sh[tid] += t;
        __syncthreads();
    }
    g_bsumx[tid] = sh[tid] - v;   // exclusive
}

__global__ void scan3_kernel(int N, int Etot) {
    int i = blockIdx.x * blockDim.x + threadIdx.x;
    if (i < N) {
        int r = g_rowptr[i] + g_bsumx[i >> 8];
        g_rowptr[i] = r;
        g_cursor[i] = r;
    }
    if (i == 0) g_rowptr[N] = Etot;
}

__global__ void scatter_kernel(const void* __restrict__ ei, long E, int N) {
    long idx = (long)blockIdx.x * blockDim.x + threadIdx.x;
    if (idx >= E + N) return;
    int s, d;
    load_edge(ei, E, idx, s, d);
    int pos = atomicAdd(&g_cursor[d], 1);
    g_srcs[pos] = s;
}

// SGEMM: H[N,64] = X[N,512] @ W[512,64]   (BM=128, BN=64, BK=16, 256 thr, 8x4 microtile)
__global__ void gemm1_kernel(const float* __restrict__ X, const float* __restrict__ W,
                             int N) {
    __shared__ float As[16][128];
    __shared__ float Bs[16][64];
    int tid = threadIdx.x;
    int blockRow = blockIdx.x * 128;
    int ty = tid >> 4;
    int tx = tid & 15;
    int aRow = tid >> 2;
    int aCol = (tid & 3) * 4;
    int bRow = tid >> 4;
    int bCol = (tid & 15) * 4;

    float acc[8][4];
#pragma unroll
    for (int i = 0; i < 8; i++)
#pragma unroll
        for (int j = 0; j < 4; j++) acc[i][j] = 0.0f;

    for (int k0 = 0; k0 < F_IN; k0 += 16) {
#pragma unroll
        for (int r = 0; r < 2; r++) {
            int row = blockRow + aRow + r * 64;
            float4 v = make_float4(0.f, 0.f, 0.f, 0.f);
            if (row < N) v = *(const float4*)(X + (long)row * F_IN + k0 + aCol);
            As[aCol + 0][aRow + r * 64] = v.x;
            As[aCol + 1][aRow + r * 64] = v.y;
            As[aCol + 2][aRow + r * 64] = v.z;
            As[aCol + 3][aRow + r * 64] = v.w;
        }
        *(float4*)&Bs[bRow][bCol] = *(const float4*)(W + (long)(k0 + bRow) * 64 + bCol);
        __syncthreads();
#pragma unroll
        for (int k = 0; k < 16; k++) {
            float a[8], b[4];
            float4 a0 = *(const float4*)&As[k][ty * 8];
            float4 a1 = *(const float4*)&As[k][ty * 8 + 4];
            a[0] = a0.x; a[1] = a0.y; a[2] = a0.z; a[3] = a0.w;
            a[4] = a1.x; a[5] = a1.y; a[6] = a1.z; a[7] = a1.w;
            float4 b0 = *(const float4*)&Bs[k][tx * 4];
            b[0] = b0.x; b[1] = b0.y; b[2] = b0.z; b[3] = b0.w;
#pragma unroll
            for (int i = 0; i < 8; i++)
#pragma unroll
                for (int j = 0; j < 4; j++) acc[i][j] = fmaf(a[i], b[j], acc[i][j]);
        }
        __syncthreads();
    }
#pragma unroll
    for (int i = 0; i < 8; i++) {
        int row = blockRow + ty * 8 + i;
        if (row < N) {
            float4 v = make_float4(acc[i][0], acc[i][1], acc[i][2], acc[i][3]);
            *(float4*)(g_h1 + (long)row * 64 + tx * 4) = v;
        }
    }
}

// per (node, head): attention dot products
__global__ void attn1_kernel(const float* __restrict__ asrc, const float* __restrict__ adst,
                             int N) {
    int gid = blockIdx.x * blockDim.x + threadIdx.x;
    if (gid >= N * NHEAD) return;
    int n = gid >> 3, h = gid & 7;
    float s = 0.0f, d = 0.0f;
#pragma unroll
    for (int j = 0; j < HDIM; j++) {
        float hv = g_h1[(long)n * H1DIM + h * HDIM + j];
        s = fmaf(hv, asrc[h * HDIM + j], s);
        d = fmaf(hv, adst[h * HDIM + j], d);
    }
    g_asrc1[gid] = s;
    g_adst1[gid] = d;
}

// fused layer-1 aggregation: warp per dst node, gather over CSR, no atomics.
// pass1: per-head max; pass2: softmax-weighted accumulate of 64 channels
// (lane owns channels lane and lane+32); finalize: /den + bias + ELU -> g_h2.
__global__ void agg1_kernel(const float* __restrict__ b1, int N) {
    int w = (int)(((long)blockIdx.x * blockDim.x + threadIdx.x) >> 5);
    int lane = threadIdx.x & 31;
    if (w >= N) return;
    int begin = g_rowptr[w], end = g_rowptr[w + 1];

    float adst[8];
#pragma unroll
    for (int h = 0; h < NHEAD; h++) adst[h] = g_adst1[(long)w * NHEAD + h];

    const float NEGINF = __int_as_float(0xff800000);
    float mx[8];
#pragma unroll
    for (int h = 0; h < NHEAD; h++) mx[h] = NEGINF;

    for (int i = begin + lane; i < end; i += 32) {
        int s = g_srcs[i];
        const float4* ap = (const float4*)&g_asrc1[(long)s * NHEAD];
        float4 a0 = ap[0], a1 = ap[1];
        mx[0] = fmaxf(mx[0], lrelu(a0.x + adst[0]));
        mx[1] = fmaxf(mx[1], lrelu(a0.y + adst[1]));
        mx[2] = fmaxf(mx[2], lrelu(a0.z + adst[2]));
        mx[3] = fmaxf(mx[3], lrelu(a0.w + adst[3]));
        mx[4] = fmaxf(mx[4], lrelu(a1.x + adst[4]));
        mx[5] = fmaxf(mx[5], lrelu(a1.y + adst[5]));
        mx[6] = fmaxf(mx[6], lrelu(a1.z + adst[6]));
        mx[7] = fmaxf(mx[7], lrelu(a1.w + adst[7]));
    }
#pragma unroll
    for (int h = 0; h < NHEAD; h++)
#pragma unroll
        for (int off = 16; off > 0; off >>= 1)
            mx[h] = fmaxf(mx[h], __shfl_xor_sync(0xffffffff, mx[h], off));

    int c0 = lane, c1 = lane + 32;
    int h0 = lane >> 3;        // head of c0: 0..3
    int h1h = 4 + (lane >> 3); // head of c1: 4..7
    float m0 = mx[h0], m1 = mx[h1h];
    float ad0 = adst[h0], ad1 = adst[h1h];
    float acc0 = 0.0f, acc1 = 0.0f, den0 = 0.0f, den1 = 0.0f;

    for (int i = begin; i < end; i++) {
        int s = g_srcs[i];   // uniform across warp -> broadcast
        float p0 = __expf(lrelu(g_asrc1[(long)s * NHEAD + h0] + ad0) - m0);
        float p1 = __expf(lrelu(g_asrc1[(long)s * NHEAD + h1h] + ad1) - m1);
        acc0 = fmaf(p0, g_h1[(long)s * H1DIM + c0], acc0);
        acc1 = fmaf(p1, g_h1[(long)s * H1DIM + c1], acc1);
        den0 += p0;
        den1 += p1;
    }
    float v0 = acc0 / (den0 + EPSV) + b1[c0];
    float v1 = acc1 / (den1 + EPSV) + b1[c1];
    g_h2[(long)w * H1DIM + c0] = v0 > 0.0f ? v0 : (__expf(v0) - 1.0f);
    g_h2[(long)w * H1DIM + c1] = v1 > 0.0f ? v1 : (__expf(v1) - 1.0f);
}

// warp per node: z = h2 @ W2 (K=64, 10 classes) + attention scalars
__global__ void gemm2_kernel(const float* __restrict__ W2, const float* __restrict__ as2v,
                             const float* __restrict__ ad2v, int N) {
    long warp = ((long)blockIdx.x * blockDim.x + threadIdx.x) >> 5;
    int lane = threadIdx.x & 31;
    if (warp >= N) return;
    const float* hrow = g_h2 + warp * H1DIM;
    float z = 0.0f;
    if (lane < NC) {
#pragma unroll
        for (int k = 0; k < H1DIM; k++) z = fmaf(hrow[k], W2[k * NC + lane], z);
        g_z2[warp * NC + lane] = z;
    }
    float s = (lane < NC) ? z * as2v[lane] : 0.0f;
    float d = (lane < NC) ? z * ad2v[lane] : 0.0f;
#pragma unroll
    for (int off = 16; off > 0; off >>= 1) {
        s += __shfl_down_sync(0xffffffff, s, off);
        d += __shfl_down_sync(0xffffffff, d, off);
    }
    if (lane == 0) { g_as2[warp] = s; g_ad2[warp] = d; }
}

// fused layer-2 aggregation + log-softmax: warp per dst node, lane per edge.
__global__ void agg2_kernel(const float* __restrict__ b2, float* __restrict__ out,
                            int N) {
    int w = (int)(((long)blockIdx.x * blockDim.x + threadIdx.x) >> 5);
    int lane = threadIdx.x & 31;
    if (w >= N) return;
    int begin = g_rowptr[w], end = g_rowptr[w + 1];
    float ad = g_ad2[w];

    const float NEGINF = __int_as_float(0xff800000);
    float mx = NEGINF;
    for (int i = begin + lane; i < end; i += 32)
        mx = fmaxf(mx, lrelu(g_as2[g_srcs[i]] + ad));
#pragma unroll
    for (int off = 16; off > 0; off >>= 1)
        mx = fmaxf(mx, __shfl_xor_sync(0xffffffff, mx, off));

    float acc[NC];
#pragma unroll
    for (int c = 0; c < NC; c++) acc[c] = 0.0f;
    float den = 0.0f;

    for (int i = begin + lane; i < end; i += 32) {
        int s = g_srcs[i];
        float p = __expf(lrelu(g_as2[s] + ad) - mx);
        den += p;
        const float2* zp = (const float2*)&g_z2[(long)s * NC];
#pragma unroll
        for (int j = 0; j < 5; j++) {
            float2 z = zp[j];
            acc[2 * j]     = fmaf(p, z.x, acc[2 * j]);
            acc[2 * j + 1] = fmaf(p, z.y, acc[2 * j + 1]);
        }
    }
#pragma unroll
    for (int off = 16; off > 0; off >>= 1) {
        den += __shfl_xor_sync(0xffffffff, den, off);
#pragma unroll
        for (int c = 0; c < NC; c++)
            acc[c] += __shfl_xor_sync(0xffffffff, acc[c], off);
    }
    if (lane == 0) {
        float inv = 1.0f / (den + EPSV);
        float v[NC], m = NEGINF;
#pragma unroll
        for (int c = 0; c < NC; c++) {
            v[c] = acc[c] * inv + b2[c];
            m = fmaxf(m, v[c]);
        }
        float s = 0.0f;
#pragma unroll
        for (int c = 0; c < NC; c++) s += __expf(v[c] - m);
        float lse = logf(s);
#pragma unroll
        for (int c = 0; c < NC; c++) out[(long)w * NC + c] = v[c] - m - lse;
    }
}

// ---------------- launch ----------------
extern "C" void kernel_launch(void* const* d_in, const int* in_sizes, int n_in,
                              void* d_out, int out_size) {
    const float* x    = (const float*)d_in[0];
    const float* W1   = (const float*)d_in[1];
    const float* as1  = (const float*)d_in[2];
    const float* ad1  = (const float*)d_in[3];
    const float* b1   = (const float*)d_in[4];
    const float* W2   = (const float*)d_in[5];
    const float* as2  = (const float*)d_in[6];
    const float* ad2  = (const float*)d_in[7];
    const float* b2   = (const float*)d_in[8];
    const void*  ei   = d_in[9];
    float* out = (float*)d_out;

    int N = in_sizes[0] / F_IN;
    long E = (long)in_sizes[9] / 2;
    long Etot = E + N;
    int nblk = (N + 255) / 256;

    detect_idx_kernel<<<1, 1>>>((const unsigned int*)ei);

    // ---- CSR build (dst-sorted incoming edges) ----
    zero_deg_kernel<<<nblk, 256>>>(N);
    hist_kernel<<<(unsigned)((Etot + 255) / 256), 256>>>(ei, E, N);
    scan1_kernel<<<nblk, 256>>>(N);
    scan2_kernel<<<1, 512>>>(nblk);
    scan3_kernel<<<nblk, 256>>>(N, (int)Etot);
    scatter_kernel<<<(unsigned)((Etot + 255) / 256), 256>>>(ei, E, N);

    // ---- layer 1 ----
    gemm1_kernel<<<(N + 127) / 128, 256>>>(x, W1, N);
    attn1_kernel<<<(N * NHEAD + 255) / 256, 256>>>(as1, ad1, N);
    agg1_kernel<<<(unsigned)(((long)N * 32 + 255) / 256), 256>>>(b1, N);

    // ---- layer 2 ----
    gemm2_kernel<<<(unsigned)(((long)N * 32 + 255) / 256), 256>>>(W2, as2, ad2, N);
    agg2_kernel<<<(unsigned)(((long)N * 32 + 255) / 256), 256>>>(b2, out, N);
}